// round 7
// baseline (speedup 1.0000x reference)
#include <cuda_runtime.h>

#define W_IMG 1920
#define H_IMG 1080
#define HW (W_IMG * H_IMG)
#define GRID_Y 16
#define GRID_X 16
#define GRID_L 8
#define GRID_ELEMS (GRID_Y * GRID_X * GRID_L * 12)

#define ROWS 4          // rows per block; 1080/4 = 270
#define SLAB 288        // 3 xcols * 8 z * 12 coeffs
#define XCOL_STRIDE 96  // 8 z * 12

// Block: 128 threads = 128 consecutive pixels, processing ROWS consecutive
// image rows. Per block we load the RAW grid (3 y-levels x 3 x-cols) into smem
// once, then per row build the y-blended slab from smem (double-buffered, one
// __syncthreads per row) and do the 4-corner (x,z) bilinear per pixel.
// x-interpolation state is row-invariant and hoisted out of the row loop.

__global__ __launch_bounds__(128)
void bilateral_grid_kernel(const float* __restrict__ rgb,
                           const float* __restrict__ grids,
                           const int*   __restrict__ idx_p,
                           float* __restrict__ out)
{
    __shared__ __align__(16) float raw[3 * SLAB];    // 3 y-levels
    __shared__ __align__(16) float slab[2][SLAB];    // double-buffered blended

    const int tid  = threadIdx.x;
    const int yrow0 = blockIdx.y * ROWS;
    const int x    = blockIdx.x * 128 + tid;

    // ---- band y-levels: rows span <=2 cells -> levels ybase..ybase+2 ----
    float gy0 = (float)yrow0 * (15.0f / 1079.0f);
    int ybase = (int)floorf(gy0);
    if (ybase > GRID_Y - 1) ybase = GRID_Y - 1;

    // ---- block's base grid x-column ----
    float gx_first = (float)(blockIdx.x * 128) * (15.0f / 1919.0f);
    int xc0 = (int)floorf(gx_first);

    const float* G = grids + idx_p[0] * GRID_ELEMS;

    // ---- load 3 raw y-levels x 3 x-cols (clamped) : 864 floats ----
    #pragma unroll
    for (int i = tid; i < 3 * SLAB; i += 128) {
        int lvl  = i / SLAB;
        int rem  = i - lvl * SLAB;              // xcol*96 + z*12 + q
        int xcol = rem / XCOL_STRIDE;
        int rem2 = rem - xcol * XCOL_STRIDE;
        int gyl  = min(ybase + lvl, GRID_Y - 1);
        int gxc  = min(xc0 + xcol, GRID_X - 1);
        raw[i] = __ldg(G + ((gyl * GRID_X + gxc) * GRID_L) * 12 + rem2);
    }

    // ---- hoisted per-pixel x interpolation (row-invariant) ----
    float gxp = (float)x * (15.0f / 1919.0f);
    float fx  = floorf(gxp);
    float wx  = gxp - fx;
    float owx = 1.0f - wx;
    int x0    = (int)fx;
    int b0    = (x0 - xc0) * XCOL_STRIDE;                       // lx0 * 96
    int b1    = (min(x0 + 1, GRID_X - 1) - xc0) * XCOL_STRIDE;  // lx1 * 96

    __syncthreads();   // raw ready

    #pragma unroll
    for (int rr = 0; rr < ROWS; rr++) {
        const int y = yrow0 + rr;

        // ---- build y-blended slab for this row (from smem raw) ----
        float gy = (float)y * (15.0f / 1079.0f);
        float fy = floorf(gy);
        float wy = gy - fy;
        int y0 = (int)fy;
        if (y0 > GRID_Y - 1) y0 = GRID_Y - 1;
        int l0 = y0 - ybase;
        int l1 = min(y0 + 1, GRID_Y - 1) - ybase;

        float* sl = slab[rr & 1];
        #pragma unroll
        for (int i = tid; i < SLAB; i += 128) {
            float a = raw[l0 * SLAB + i];
            float b = raw[l1 * SLAB + i];
            sl[i] = fmaf(wy, b - a, a);
        }
        __syncthreads();   // slab ready; also proves main(rr-1) done block-wide

        // ---- per-pixel main work ----
        const int pix = y * W_IMG + x;
        float r = __ldg(rgb + pix);
        float g = __ldg(rgb + HW + pix);
        float b = __ldg(rgb + 2 * HW + pix);

        float gray = 0.299f * r + 0.587f * g + 0.114f * b;
        gray = fminf(fmaxf(gray, 0.0f), 1.0f);

        float gz = gray * 7.0f;
        float fz = floorf(gz);
        float wz = gz - fz;
        int z0 = (int)fz;
        if (z0 > GRID_L - 1) z0 = GRID_L - 1;
        int z1 = min(z0 + 1, GRID_L - 1);

        float owz = 1.0f - wz;
        float w00 = owx * owz;
        float w01 = owx * wz;
        float w10 = wx * owz;
        float w11 = wx * wz;

        const float4* c00 = (const float4*)(sl + b0 + z0 * 12);
        const float4* c01 = (const float4*)(sl + b0 + z1 * 12);
        const float4* c10 = (const float4*)(sl + b1 + z0 * 12);
        const float4* c11 = (const float4*)(sl + b1 + z1 * 12);

        float4 a0, a1, a2;
        {
            float4 p00 = c00[0], p01 = c01[0], p10 = c10[0], p11 = c11[0];
            a0.x = w00 * p00.x + w01 * p01.x + w10 * p10.x + w11 * p11.x;
            a0.y = w00 * p00.y + w01 * p01.y + w10 * p10.y + w11 * p11.y;
            a0.z = w00 * p00.z + w01 * p01.z + w10 * p10.z + w11 * p11.z;
            a0.w = w00 * p00.w + w01 * p01.w + w10 * p10.w + w11 * p11.w;
        }
        {
            float4 p00 = c00[1], p01 = c01[1], p10 = c10[1], p11 = c11[1];
            a1.x = w00 * p00.x + w01 * p01.x + w10 * p10.x + w11 * p11.x;
            a1.y = w00 * p00.y + w01 * p01.y + w10 * p10.y + w11 * p11.y;
            a1.z = w00 * p00.z + w01 * p01.z + w10 * p10.z + w11 * p11.z;
            a1.w = w00 * p00.w + w01 * p01.w + w10 * p10.w + w11 * p11.w;
        }
        {
            float4 p00 = c00[2], p01 = c01[2], p10 = c10[2], p11 = c11[2];
            a2.x = w00 * p00.x + w01 * p01.x + w10 * p10.x + w11 * p11.x;
            a2.y = w00 * p00.y + w01 * p01.y + w10 * p10.y + w11 * p11.y;
            a2.z = w00 * p00.z + w01 * p01.z + w10 * p10.z + w11 * p11.z;
            a2.w = w00 * p00.w + w01 * p01.w + w10 * p10.w + w11 * p11.w;
        }

        // affine_mat: out[pix*12 .. pix*12+11]
        float4* oa = (float4*)(out + (size_t)pix * 12);
        oa[0] = a0;
        oa[1] = a1;
        oa[2] = a2;

        // res_rgb: out[12*HW + pix*3 ...]
        float* orr = out + (size_t)12 * HW + (size_t)pix * 3;
        orr[0] = a0.x * r + a0.y * g + a0.z * b + a0.w;
        orr[1] = a1.x * r + a1.y * g + a1.z * b + a1.w;
        orr[2] = a2.x * r + a2.y * g + a2.z * b + a2.w;
    }
}

extern "C" void kernel_launch(void* const* d_in, const int* in_sizes, int n_in,
                              void* d_out, int out_size)
{
    const float* rgb   = (const float*)d_in[0];
    const float* grids = (const float*)d_in[1];
    const int*   idx   = (const int*)d_in[2];
    float* out = (float*)d_out;

    dim3 grid(W_IMG / 128, H_IMG / ROWS);
    bilateral_grid_kernel<<<grid, 128>>>(rgb, grids, idx, out);
}

// round 8
// speedup vs baseline: 1.1284x; 1.1284x over previous
#include <cuda_runtime.h>

#define W_IMG 1920
#define H_IMG 1080
#define HW (W_IMG * H_IMG)
#define GRID_Y 16
#define GRID_X 16
#define GRID_L 8
#define GRID_ELEMS (GRID_Y * GRID_X * GRID_L * 12)

#define SLAB 288        // 3 xcols * 8 z * 12 coeffs
#define XCOL_STRIDE 96  // 8 z * 12

// Block: 128 threads = 128 consecutive pixels of ONE image row (grid 15 x 1080).
// Per block: y-blended slab (3 x-cols) built once in smem; per pixel a 4-corner
// (x,z) bilinear gather from smem.
// NEW: affine_mat output is repacked through per-warp smem staging so the
// global stores are fully coalesced (12 wavefronts per warp instead of 36).

__global__ __launch_bounds__(128)
void bilateral_grid_kernel(const float* __restrict__ rgb,
                           const float* __restrict__ grids,
                           const int*   __restrict__ idx_p,
                           float* __restrict__ out)
{
    __shared__ __align__(16) float slab[SLAB];        // 1.15 KB
    __shared__ __align__(16) float stage[4][32 * 12]; // 4 warps x 1536 B

    const int tid = threadIdx.x;
    const int wid = tid >> 5;
    const int lid = tid & 31;
    const int y   = blockIdx.y;
    const int x   = blockIdx.x * 128 + tid;
    const int pix = y * W_IMG + x;

    // ---- issue rgb loads early; latency hides under slab build ----
    float r = __ldg(rgb + pix);
    float g = __ldg(rgb + HW + pix);
    float b = __ldg(rgb + 2 * HW + pix);

    // ---- per-row y interpolation (uniform across block) ----
    float gy = (float)y * (15.0f / 1079.0f);
    float fy = floorf(gy);
    float wy = gy - fy;
    int y0 = (int)fy;
    if (y0 > GRID_Y - 1) y0 = GRID_Y - 1;
    int y1 = min(y0 + 1, GRID_Y - 1);

    // ---- block's base grid x-column ----
    float gx_first = (float)(blockIdx.x * 128) * (15.0f / 1919.0f);
    int xc0 = (int)floorf(gx_first);

    const float* G = grids + idx_p[0] * GRID_ELEMS;

    // ---- build y-blended slab: 3 xcols x 8 z x 12 coeffs ----
    #pragma unroll
    for (int i = tid; i < SLAB; i += 128) {
        int xcol = i / XCOL_STRIDE;
        int rem  = i - xcol * XCOL_STRIDE;
        int gxc  = min(xc0 + xcol, GRID_X - 1);
        int base0 = ((y0 * GRID_X + gxc) * GRID_L) * 12 + rem;
        int base1 = ((y1 * GRID_X + gxc) * GRID_L) * 12 + rem;
        float a = __ldg(G + base0);
        float bb = __ldg(G + base1);
        slab[i] = fmaf(wy, bb - a, a);
    }
    __syncthreads();

    // ---- per-pixel interpolation setup ----
    float gray = 0.299f * r + 0.587f * g + 0.114f * b;
    gray = fminf(fmaxf(gray, 0.0f), 1.0f);

    float gz = gray * 7.0f;
    float fz = floorf(gz);
    float wz = gz - fz;
    int z0 = (int)fz;
    if (z0 > GRID_L - 1) z0 = GRID_L - 1;
    int z1 = min(z0 + 1, GRID_L - 1);

    float gxp = (float)x * (15.0f / 1919.0f);
    float fx = floorf(gxp);
    float wx = gxp - fx;
    int x0  = (int)fx;
    int b0  = (x0 - xc0) * XCOL_STRIDE;
    int b1  = (min(x0 + 1, GRID_X - 1) - xc0) * XCOL_STRIDE;

    float owx = 1.0f - wx;
    float owz = 1.0f - wz;
    float w00 = owx * owz;
    float w01 = owx * wz;
    float w10 = wx * owz;
    float w11 = wx * wz;

    const float4* c00 = (const float4*)(slab + b0 + z0 * 12);
    const float4* c01 = (const float4*)(slab + b0 + z1 * 12);
    const float4* c10 = (const float4*)(slab + b1 + z0 * 12);
    const float4* c11 = (const float4*)(slab + b1 + z1 * 12);

    float4 a0, a1, a2;
    {
        float4 p00 = c00[0], p01 = c01[0], p10 = c10[0], p11 = c11[0];
        a0.x = w00 * p00.x + w01 * p01.x + w10 * p10.x + w11 * p11.x;
        a0.y = w00 * p00.y + w01 * p01.y + w10 * p10.y + w11 * p11.y;
        a0.z = w00 * p00.z + w01 * p01.z + w10 * p10.z + w11 * p11.z;
        a0.w = w00 * p00.w + w01 * p01.w + w10 * p10.w + w11 * p11.w;
    }
    {
        float4 p00 = c00[1], p01 = c01[1], p10 = c10[1], p11 = c11[1];
        a1.x = w00 * p00.x + w01 * p01.x + w10 * p10.x + w11 * p11.x;
        a1.y = w00 * p00.y + w01 * p01.y + w10 * p10.y + w11 * p11.y;
        a1.z = w00 * p00.z + w01 * p01.z + w10 * p10.z + w11 * p11.z;
        a1.w = w00 * p00.w + w01 * p01.w + w10 * p10.w + w11 * p11.w;
    }
    {
        float4 p00 = c00[2], p01 = c01[2], p10 = c10[2], p11 = c11[2];
        a2.x = w00 * p00.x + w01 * p01.x + w10 * p10.x + w11 * p11.x;
        a2.y = w00 * p00.y + w01 * p01.y + w10 * p10.y + w11 * p11.y;
        a2.z = w00 * p00.z + w01 * p01.z + w10 * p10.z + w11 * p11.z;
        a2.w = w00 * p00.w + w01 * p01.w + w10 * p10.w + w11 * p11.w;
    }

    // ---- res_rgb: direct store (small) ----
    float* orr = out + (size_t)12 * HW + (size_t)pix * 3;
    orr[0] = a0.x * r + a0.y * g + a0.z * b + a0.w;
    orr[1] = a1.x * r + a1.y * g + a1.z * b + a1.w;
    orr[2] = a2.x * r + a2.y * g + a2.z * b + a2.w;

    // ---- affine_mat: repack via per-warp staging, then coalesced STG ----
    {
        float4* st = (float4*)(stage[wid] + lid * 12);   // lid*48B: banks 12*lid mod 32, conflict-free
        st[0] = a0;
        st[1] = a1;
        st[2] = a2;
        __syncwarp();

        const float4* s4 = (const float4*)stage[wid];
        // warp's output region: 32 px * 12 floats = 1536 B contiguous
        float4* op = (float4*)(out + ((size_t)y * W_IMG + blockIdx.x * 128 + wid * 32) * 12);
        op[lid]      = s4[lid];
        op[lid + 32] = s4[lid + 32];
        op[lid + 64] = s4[lid + 64];
    }
}

extern "C" void kernel_launch(void* const* d_in, const int* in_sizes, int n_in,
                              void* d_out, int out_size)
{
    const float* rgb   = (const float*)d_in[0];
    const float* grids = (const float*)d_in[1];
    const int*   idx   = (const int*)d_in[2];
    float* out = (float*)d_out;

    dim3 grid(W_IMG / 128, H_IMG);
    bilateral_grid_kernel<<<grid, 128>>>(rgb, grids, idx, out);
}

// round 9
// speedup vs baseline: 1.1913x; 1.0558x over previous
#include <cuda_runtime.h>

#define W_IMG 1920
#define H_IMG 1080
#define HW (W_IMG * H_IMG)
#define GRID_Y 16
#define GRID_X 16
#define GRID_L 8
#define GRID_ELEMS (GRID_Y * GRID_X * GRID_L * 12)

#define SLAB 288        // 3 xcols * 8 z * 12 coeffs
#define XCOL_STRIDE 96  // 8 z * 12

// Block: 128 threads = 128 consecutive x positions, TWO image rows (y, y+1).
// grid = (1920/128 = 15, 1080/2 = 540).
// Per block: two y-blended slabs in smem (one per row); per thread two
// independent 4-corner (x,z) bilinear chains (ILP=2). x-interp state is shared
// between rows. affine_mat stores are repacked via per-warp smem staging
// (double-buffered across rows -> single __syncwarp) into fully coalesced STG.

__device__ __forceinline__ void blend4(const float* __restrict__ sl,
                                       int b0, int b1, int z0, int z1,
                                       float w00, float w01, float w10, float w11,
                                       float4& a0, float4& a1, float4& a2)
{
    const float4* c00 = (const float4*)(sl + b0 + z0 * 12);
    const float4* c01 = (const float4*)(sl + b0 + z1 * 12);
    const float4* c10 = (const float4*)(sl + b1 + z0 * 12);
    const float4* c11 = (const float4*)(sl + b1 + z1 * 12);
    #pragma unroll
    for (int q = 0; q < 3; q++) {
        float4 p00 = c00[q], p01 = c01[q], p10 = c10[q], p11 = c11[q];
        float4 a;
        a.x = w00 * p00.x + w01 * p01.x + w10 * p10.x + w11 * p11.x;
        a.y = w00 * p00.y + w01 * p01.y + w10 * p10.y + w11 * p11.y;
        a.z = w00 * p00.z + w01 * p01.z + w10 * p10.z + w11 * p11.z;
        a.w = w00 * p00.w + w01 * p01.w + w10 * p10.w + w11 * p11.w;
        if (q == 0) a0 = a; else if (q == 1) a1 = a; else a2 = a;
    }
}

__global__ __launch_bounds__(128)
void bilateral_grid_kernel(const float* __restrict__ rgb,
                           const float* __restrict__ grids,
                           const int*   __restrict__ idx_p,
                           float* __restrict__ out)
{
    __shared__ __align__(16) float slab[2][SLAB];           // 2.3 KB
    __shared__ __align__(16) float stage[4][2][32 * 12];    // 12.3 KB

    const int tid = threadIdx.x;
    const int wid = tid >> 5;
    const int lid = tid & 31;
    const int yA  = blockIdx.y * 2;
    const int yB  = yA + 1;
    const int x   = blockIdx.x * 128 + tid;
    const int pixA = yA * W_IMG + x;
    const int pixB = pixA + W_IMG;

    // ---- rgb loads for both rows issued early ----
    float rA = __ldg(rgb + pixA);
    float gA = __ldg(rgb + HW + pixA);
    float bA = __ldg(rgb + 2 * HW + pixA);
    float rB = __ldg(rgb + pixB);
    float gB = __ldg(rgb + HW + pixB);
    float bB = __ldg(rgb + 2 * HW + pixB);

    // ---- per-row y interpolation (uniform across block) ----
    float gyA = (float)yA * (15.0f / 1079.0f);
    float fyA = floorf(gyA);
    float wyA = gyA - fyA;
    int yA0 = (int)fyA; if (yA0 > GRID_Y - 1) yA0 = GRID_Y - 1;
    int yA1 = min(yA0 + 1, GRID_Y - 1);

    float gyB = (float)yB * (15.0f / 1079.0f);
    float fyB = floorf(gyB);
    float wyB = gyB - fyB;
    int yB0 = (int)fyB; if (yB0 > GRID_Y - 1) yB0 = GRID_Y - 1;
    int yB1 = min(yB0 + 1, GRID_Y - 1);

    // ---- block's base grid x-column ----
    float gx_first = (float)(blockIdx.x * 128) * (15.0f / 1919.0f);
    int xc0 = (int)floorf(gx_first);

    const float* G = grids + idx_p[0] * GRID_ELEMS;

    // ---- build both y-blended slabs: 2 x 288 ----
    #pragma unroll
    for (int i = tid; i < 2 * SLAB; i += 128) {
        int rowsel = (i >= SLAB) ? 1 : 0;
        int j = i - rowsel * SLAB;
        int xcol = j / XCOL_STRIDE;
        int rem  = j - xcol * XCOL_STRIDE;
        int gxc  = min(xc0 + xcol, GRID_X - 1);
        int yy0 = rowsel ? yB0 : yA0;
        int yy1 = rowsel ? yB1 : yA1;
        float wy = rowsel ? wyB : wyA;
        float a  = __ldg(G + ((yy0 * GRID_X + gxc) * GRID_L) * 12 + rem);
        float bb = __ldg(G + ((yy1 * GRID_X + gxc) * GRID_L) * 12 + rem);
        slab[rowsel][j] = fmaf(wy, bb - a, a);
    }

    // ---- hoisted x interpolation (identical for both rows) ----
    float gxp = (float)x * (15.0f / 1919.0f);
    float fx = floorf(gxp);
    float wx = gxp - fx;
    float owx = 1.0f - wx;
    int x0  = (int)fx;
    int b0  = (x0 - xc0) * XCOL_STRIDE;
    int b1  = (min(x0 + 1, GRID_X - 1) - xc0) * XCOL_STRIDE;

    __syncthreads();

    // ---- row A z setup ----
    float grayA = 0.299f * rA + 0.587f * gA + 0.114f * bA;
    grayA = fminf(fmaxf(grayA, 0.0f), 1.0f);
    float gzA = grayA * 7.0f;
    float fzA = floorf(gzA);
    float wzA = gzA - fzA;
    int zA0 = (int)fzA; if (zA0 > GRID_L - 1) zA0 = GRID_L - 1;
    int zA1 = min(zA0 + 1, GRID_L - 1);

    // ---- row B z setup ----
    float grayB = 0.299f * rB + 0.587f * gB + 0.114f * bB;
    grayB = fminf(fmaxf(grayB, 0.0f), 1.0f);
    float gzB = grayB * 7.0f;
    float fzB = floorf(gzB);
    float wzB = gzB - fzB;
    int zB0 = (int)fzB; if (zB0 > GRID_L - 1) zB0 = GRID_L - 1;
    int zB1 = min(zB0 + 1, GRID_L - 1);

    // ---- two independent 4-corner blends (ILP) ----
    float4 aA0, aA1, aA2, aB0, aB1, aB2;
    {
        float owzA = 1.0f - wzA;
        blend4(slab[0], b0, b1, zA0, zA1,
               owx * owzA, owx * wzA, wx * owzA, wx * wzA, aA0, aA1, aA2);
    }
    {
        float owzB = 1.0f - wzB;
        blend4(slab[1], b0, b1, zB0, zB1,
               owx * owzB, owx * wzB, wx * owzB, wx * wzB, aB0, aB1, aB2);
    }

    // ---- res_rgb direct stores (both rows) ----
    float* orrA = out + (size_t)12 * HW + (size_t)pixA * 3;
    orrA[0] = aA0.x * rA + aA0.y * gA + aA0.z * bA + aA0.w;
    orrA[1] = aA1.x * rA + aA1.y * gA + aA1.z * bA + aA1.w;
    orrA[2] = aA2.x * rA + aA2.y * gA + aA2.z * bA + aA2.w;
    float* orrB = out + (size_t)12 * HW + (size_t)pixB * 3;
    orrB[0] = aB0.x * rB + aB0.y * gB + aB0.z * bB + aB0.w;
    orrB[1] = aB1.x * rB + aB1.y * gB + aB1.z * bB + aB1.w;
    orrB[2] = aB2.x * rB + aB2.y * gB + aB2.z * bB + aB2.w;

    // ---- affine_mat: stage both rows, one syncwarp, coalesced stores ----
    {
        float4* stA = (float4*)(stage[wid][0] + lid * 12);
        stA[0] = aA0; stA[1] = aA1; stA[2] = aA2;
        float4* stB = (float4*)(stage[wid][1] + lid * 12);
        stB[0] = aB0; stB[1] = aB1; stB[2] = aB2;
        __syncwarp();

        const int warp_x = blockIdx.x * 128 + wid * 32;
        const float4* sA = (const float4*)stage[wid][0];
        float4* opA = (float4*)(out + ((size_t)yA * W_IMG + warp_x) * 12);
        opA[lid]      = sA[lid];
        opA[lid + 32] = sA[lid + 32];
        opA[lid + 64] = sA[lid + 64];

        const float4* sB = (const float4*)stage[wid][1];
        float4* opB = (float4*)(out + ((size_t)yB * W_IMG + warp_x) * 12);
        opB[lid]      = sB[lid];
        opB[lid + 32] = sB[lid + 32];
        opB[lid + 64] = sB[lid + 64];
    }
}

extern "C" void kernel_launch(void* const* d_in, const int* in_sizes, int n_in,
                              void* d_out, int out_size)
{
    const float* rgb   = (const float*)d_in[0];
    const float* grids = (const float*)d_in[1];
    const int*   idx   = (const int*)d_in[2];
    float* out = (float*)d_out;

    dim3 grid(W_IMG / 128, H_IMG / 2);
    bilateral_grid_kernel<<<grid, 128>>>(rgb, grids, idx, out);
}